// round 4
// baseline (speedup 1.0000x reference)
#include <cuda_runtime.h>
#include <cstdint>

// Problem dims (fixed by dataset)
#define BDIM   8
#define PDIM   120000
#define NCLS   5
#define CFG    4            // foreground classes
#define NPAIR  (BDIM * CFG) // 32 independent (image, class) problems
#define TOPK   1000
#define NBINS  16384
#define CAP    4096         // candidate buffer (pow2, bitonic sort size)
#define NWORDS 16           // ceil(TOPK/64)

typedef unsigned long long u64;
typedef unsigned int u32;

// ---- static device scratch (no allocations allowed) ----
__device__ float g_scores[NPAIR * PDIM];            // 15.36 MB  softmax scores (bg dropped)
__device__ float4 g_cs[BDIM * PDIM];                // 15.36 MB  decoded center-size boxes
__device__ u64 g_mask[(size_t)NPAIR * TOPK * NWORDS]; // 4 MB    NMS suppression bitmatrix

// =====================================================================
// Kernel 1: fused softmax + SSD decode.
// All arithmetic via *_rn intrinsics: no FMA contraction, matches XLA's
// un-fused elementwise HLO exactly. expf == libdevice __nv_expf == XLA.
// =====================================================================
__global__ void decode_score_kernel(const float* __restrict__ loc,
                                    const float* __restrict__ conf,
                                    const float* __restrict__ prior) {
    int idx = blockIdx.x * blockDim.x + threadIdx.x;
    if (idx >= BDIM * PDIM) return;
    int b = idx / PDIM;
    int p = idx - b * PDIM;

    float4 pr = reinterpret_cast<const float4*>(prior)[p];
    const float* lb = loc + (size_t)b * 4 * PDIM + p;
    float l0 = lb[0], l1 = lb[PDIM], l2 = lb[2 * PDIM], l3 = lb[3 * PDIM];

    // cxcy = prior_cxcy + (loc*0.1)*prior_wh ; wh = prior_wh * exp(loc*0.2)
    float cx = __fadd_rn(pr.x, __fmul_rn(__fmul_rn(l0, 0.1f), pr.z));
    float cy = __fadd_rn(pr.y, __fmul_rn(__fmul_rn(l1, 0.1f), pr.w));
    float w  = __fmul_rn(pr.z, expf(__fmul_rn(l2, 0.2f)));
    float h  = __fmul_rn(pr.w, expf(__fmul_rn(l3, 0.2f)));
    g_cs[idx] = make_float4(cx, cy, w, h);

    const float* cb = conf + (size_t)b * NCLS * PDIM + p;
    float c0 = cb[0], c1 = cb[PDIM], c2 = cb[2 * PDIM], c3 = cb[3 * PDIM], c4 = cb[4 * PDIM];
    float mx = fmaxf(fmaxf(fmaxf(fmaxf(c0, c1), c2), c3), c4);
    float e0 = expf(__fsub_rn(c0, mx));
    float e1 = expf(__fsub_rn(c1, mx));
    float e2 = expf(__fsub_rn(c2, mx));
    float e3 = expf(__fsub_rn(c3, mx));
    float e4 = expf(__fsub_rn(c4, mx));
    float ssum = __fadd_rn(__fadd_rn(__fadd_rn(__fadd_rn(e0, e1), e2), e3), e4);
    size_t sb = (size_t)b * CFG * PDIM + p;
    g_scores[sb]             = __fdiv_rn(e1, ssum);
    g_scores[sb + PDIM]      = __fdiv_rn(e2, ssum);
    g_scores[sb + 2 * PDIM]  = __fdiv_rn(e3, ssum);
    g_scores[sb + 3 * PDIM]  = __fdiv_rn(e4, ssum);
}

// =====================================================================
// Kernel 2: one CTA per (image, class):
//   histogram -> exact top-K cutoff bin -> gather -> bitonic sort ->
//   IoU suppression bitmask -> serial greedy sweep (1 warp) -> compact.
// =====================================================================
__global__ void __launch_bounds__(1024, 1)
detect_pair_kernel(const float* __restrict__ conf_th_p,
                   const float* __restrict__ nms_th_p,
                   float* __restrict__ out) {
    const int pair = blockIdx.x;
    const int b = pair >> 2;
    const int tid = threadIdx.x;
    const float conf_th = *conf_th_p;
    const float nms_th  = *nms_th_p;

    extern __shared__ char sm[];
    int* hist = (int*)sm;                        // phase 1: 16384 ints = 64 KB
    u64* keys = (u64*)sm;                        // phase 2+: 4096 u64 = 32 KB (reuses hist)
    float* topscore = (float*)(sm + 32768);
    int*   topidx   = (int*)  (sm + 32768 + 4000);
    float* x1s      = (float*)(sm + 32768 + 8000);
    float* y1s      = (float*)(sm + 32768 + 12000);
    float* x2s      = (float*)(sm + 32768 + 16000);
    float* y2s      = (float*)(sm + 32768 + 20000);
    float* areas    = (float*)(sm + 32768 + 24000);

    __shared__ int scanA[1024];
    __shared__ int s_T, s_cnt;
    __shared__ u64 s_keep[NWORDS];
    __shared__ int s_pref[NWORDS];

    const float* sc = g_scores + (size_t)pair * PDIM;

    // ---- histogram of thresholded scores ----
    for (int i = tid; i < NBINS; i += 1024) hist[i] = 0;
    __syncthreads();
    for (int p = tid; p < PDIM; p += 1024) {
        float s = sc[p];
        if (s >= conf_th) {
            int bin = (int)(s * 16384.0f);
            if (bin > NBINS - 1) bin = NBINS - 1;
            atomicAdd(&hist[bin], 1);
        }
    }
    __syncthreads();

    // ---- suffix scan to find cutoff bin T (1000th-largest lives in bin T) ----
    int base = tid * 16;
    int ps = 0;
#pragma unroll
    for (int k = 0; k < 16; k++) ps += hist[base + k];
    scanA[tid] = ps;
    __syncthreads();
    for (int off = 1; off < 1024; off <<= 1) {
        int v = scanA[tid];
        if (tid + off < 1024) v += scanA[tid + off];
        __syncthreads();
        scanA[tid] = v;
        __syncthreads();
    }
    int total = scanA[0];
    if (tid == 0) { s_T = 0; s_cnt = 0; }
    __syncthreads();
    if (total >= TOPK) {
        int after = (tid < 1023) ? scanA[tid + 1] : 0;
        if (after < TOPK && after + ps >= TOPK) {
            int acc = after;
            for (int bb = 15; bb >= 0; bb--) {
                acc += hist[base + bb];
                if (acc >= TOPK) { s_T = base + bb; break; }
            }
        }
    }
    __syncthreads();
    int T = s_T;

    // ---- gather candidates (bin >= T) into shared key buffer ----
    // key = score_bits<<32 | ~idx  -> descending sort == top_k with
    // lower-index tiebreak (exact lax.top_k semantics).
    for (int p = tid; p < PDIM; p += 1024) {
        float s = sc[p];
        if (s >= conf_th) {
            int bin = (int)(s * 16384.0f);
            if (bin > NBINS - 1) bin = NBINS - 1;
            if (bin >= T) {
                int pos = atomicAdd(&s_cnt, 1);
                if (pos < CAP)
                    keys[pos] = ((u64)__float_as_uint(s) << 32) | (u32)(~(u32)p);
            }
        }
    }
    __syncthreads();
    int M = s_cnt; if (M > CAP) M = CAP;
    for (int i = M + tid; i < CAP; i += 1024) keys[i] = 0ull;
    __syncthreads();

    // ---- bitonic sort, descending, 4096 elements ----
    for (int k2 = 2; k2 <= CAP; k2 <<= 1) {
        for (int j = k2 >> 1; j > 0; j >>= 1) {
            for (int i = tid; i < CAP; i += 1024) {
                int ixj = i ^ j;
                if (ixj > i) {
                    u64 a = keys[i], c = keys[ixj];
                    bool up = ((i & k2) == 0);
                    bool sw = up ? (a < c) : (a > c);
                    if (sw) { keys[i] = c; keys[ixj] = a; }
                }
            }
            __syncthreads();
        }
    }

    int Kv = (M < TOPK) ? M : TOPK;

    // ---- extract top candidates, build point-form boxes + areas ----
    for (int i = tid; i < Kv; i += 1024) {
        u64 key = keys[i];
        int p = (int)(~(u32)key);
        float s = __uint_as_float((u32)(key >> 32));
        topscore[i] = s;
        topidx[i] = p;
        float4 csv = g_cs[(size_t)b * PDIM + p];
        float hw = __fmul_rn(csv.z, 0.5f);
        float hh = __fmul_rn(csv.w, 0.5f);
        float X1 = __fsub_rn(csv.x, hw);
        float Y1 = __fsub_rn(csv.y, hh);
        float X2 = __fadd_rn(csv.x, hw);
        float Y2 = __fadd_rn(csv.y, hh);
        x1s[i] = X1; y1s[i] = Y1; x2s[i] = X2; y2s[i] = Y2;
        areas[i] = __fmul_rn(fmaxf(__fsub_rn(X2, X1), 0.0f),
                             fmaxf(__fsub_rn(Y2, Y1), 0.0f));
    }
    __syncthreads();

    // ---- suppression bitmask: mask[i][w] bit j-j0 set iff IoU(i,j)>th, j>i ----
    u64* mrow = g_mask + (size_t)pair * TOPK * NWORDS;
    for (int W = tid; W < Kv * NWORDS; W += 1024) {
        int i = W >> 4;
        int w = W & (NWORDS - 1);
        u64 mword = 0ull;
        int j0 = w << 6;
        int jend = j0 + 64; if (jend > Kv) jend = Kv;
        int jstart = (j0 > i + 1) ? j0 : (i + 1);
        if (jstart < jend) {
            float X1 = x1s[i], Y1 = y1s[i], X2 = x2s[i], Y2 = y2s[i], ai = areas[i];
            for (int j = jstart; j < jend; j++) {
                float iw = fmaxf(__fsub_rn(fminf(X2, x2s[j]), fmaxf(X1, x1s[j])), 0.0f);
                float ih = fmaxf(__fsub_rn(fminf(Y2, y2s[j]), fmaxf(Y1, y1s[j])), 0.0f);
                float inter = __fmul_rn(iw, ih);
                float uni = __fsub_rn(__fadd_rn(ai, areas[j]), inter);
                float iou = __fdiv_rn(inter, fmaxf(uni, 1e-12f));
                if (iou > nms_th) mword |= (1ull << (j - j0));
            }
        }
        mrow[W] = mword;
    }
    __syncthreads();

    // ---- serial greedy sweep: warp 0, lane w holds keep word w ----
    if ((tid >> 5) == 0) {
        int lane = tid & 31;
        u64 keepw = 0ull;
        if (lane < NWORDS) {
            int lo = lane << 6;
            int n = Kv - lo;
            if (n >= 64) keepw = ~0ull;
            else if (n > 0) keepw = ((1ull << n) - 1ull);
        }
        u64 m = (lane < NWORDS && Kv > 0) ? mrow[lane] : 0ull;
        for (int i = 0; i < Kv; i++) {
            u64 mnext = (lane < NWORDS && (i + 1) < Kv) ? mrow[(size_t)(i + 1) * NWORDS + lane] : 0ull;
            u64 kw = __shfl_sync(0xffffffffu, keepw, i >> 6);
            if ((kw >> (i & 63)) & 1ull) keepw &= ~m;
            m = mnext;
        }
        if (lane < NWORDS) s_keep[lane] = keepw;
    }
    __syncthreads();
    if (tid == 0) {
        int acc = 0;
        for (int w = 0; w < NWORDS; w++) { s_pref[w] = acc; acc += __popcll(s_keep[w]); }
    }
    __syncthreads();

    // ---- compact kept rows to front, zeros elsewhere ----
    float* outp = out + (size_t)pair * TOPK * 5;
    for (int i = tid; i < TOPK * 5; i += 1024) outp[i] = 0.0f;
    __syncthreads();
    for (int i = tid; i < Kv; i += 1024) {
        u64 kw = s_keep[i >> 6];
        if ((kw >> (i & 63)) & 1ull) {
            int pos = s_pref[i >> 6] + __popcll(kw & ((1ull << (i & 63)) - 1ull));
            float4 csv = g_cs[(size_t)b * PDIM + topidx[i]];
            float* r = outp + pos * 5;
            r[0] = topscore[i];
            r[1] = csv.x; r[2] = csv.y; r[3] = csv.z; r[4] = csv.w;
        }
    }
}

extern "C" void kernel_launch(void* const* d_in, const int* in_sizes, int n_in,
                              void* d_out, int out_size) {
    const float* loc   = (const float*)d_in[0];
    const float* conf  = (const float*)d_in[1];
    const float* prior = (const float*)d_in[2];
    const float* cth   = (const float*)d_in[3];
    const float* nth   = (const float*)d_in[4];
    float* out = (float*)d_out;

    cudaFuncSetAttribute(detect_pair_kernel,
                         cudaFuncAttributeMaxDynamicSharedMemorySize, 65536);

    int total = BDIM * PDIM;
    decode_score_kernel<<<(total + 255) / 256, 256>>>(loc, conf, prior);
    detect_pair_kernel<<<NPAIR, 1024, 65536>>>(cth, nth, out);
}

// round 5
// speedup vs baseline: 3.8508x; 3.8508x over previous
#include <cuda_runtime.h>
#include <cstdint>

#define BDIM   8
#define PDIM   120000
#define NCLS   5
#define CFG    4
#define NPAIR  (BDIM * CFG)
#define TOPK   1000
#define NBINS  16384
#define CAP    4096
#define NWORDS 16           // u64 words per mask row
#define MCHUNK 16           // mask-build CTAs per pair

typedef unsigned long long u64;
typedef unsigned int u32;

// ---- static device scratch ----
__device__ float  g_scores[NPAIR * PDIM];
__device__ float4 g_cs[BDIM * PDIM];
__device__ u64    g_mask[(size_t)NPAIR * TOPK * NWORDS];
__device__ float4 g_box[NPAIR * 1024];      // point form (x1,y1,x2,y2), zero-padded
__device__ float  g_area[NPAIR * 1024];
__device__ float4 g_cscand[NPAIR * 1024];   // center-size of candidates
__device__ float  g_score[NPAIR * 1024];
__device__ int    g_kv[NPAIR];

// =====================================================================
// Kernel 1: fused softmax + SSD decode (exact *_rn op order == XLA HLO)
// =====================================================================
__global__ void decode_score_kernel(const float* __restrict__ loc,
                                    const float* __restrict__ conf,
                                    const float* __restrict__ prior) {
    int idx = blockIdx.x * blockDim.x + threadIdx.x;
    if (idx >= BDIM * PDIM) return;
    int b = idx / PDIM;
    int p = idx - b * PDIM;

    float4 pr = reinterpret_cast<const float4*>(prior)[p];
    const float* lb = loc + (size_t)b * 4 * PDIM + p;
    float l0 = lb[0], l1 = lb[PDIM], l2 = lb[2 * PDIM], l3 = lb[3 * PDIM];

    float cx = __fadd_rn(pr.x, __fmul_rn(__fmul_rn(l0, 0.1f), pr.z));
    float cy = __fadd_rn(pr.y, __fmul_rn(__fmul_rn(l1, 0.1f), pr.w));
    float w  = __fmul_rn(pr.z, expf(__fmul_rn(l2, 0.2f)));
    float h  = __fmul_rn(pr.w, expf(__fmul_rn(l3, 0.2f)));
    g_cs[idx] = make_float4(cx, cy, w, h);

    const float* cb = conf + (size_t)b * NCLS * PDIM + p;
    float c0 = cb[0], c1 = cb[PDIM], c2 = cb[2 * PDIM], c3 = cb[3 * PDIM], c4 = cb[4 * PDIM];
    float mx = fmaxf(fmaxf(fmaxf(fmaxf(c0, c1), c2), c3), c4);
    float e0 = expf(__fsub_rn(c0, mx));
    float e1 = expf(__fsub_rn(c1, mx));
    float e2 = expf(__fsub_rn(c2, mx));
    float e3 = expf(__fsub_rn(c3, mx));
    float e4 = expf(__fsub_rn(c4, mx));
    float ssum = __fadd_rn(__fadd_rn(__fadd_rn(__fadd_rn(e0, e1), e2), e3), e4);
    size_t sb = (size_t)b * CFG * PDIM + p;
    g_scores[sb]            = __fdiv_rn(e1, ssum);
    g_scores[sb + PDIM]     = __fdiv_rn(e2, ssum);
    g_scores[sb + 2 * PDIM] = __fdiv_rn(e3, ssum);
    g_scores[sb + 3 * PDIM] = __fdiv_rn(e4, ssum);
}

// =====================================================================
// Kernel 2: per-(image,class) exact top-K selection (32 CTAs)
//   histogram -> suffix scan -> gather candidates -> bitonic sort
//   (dynamic size) -> emit candidate arrays to global.
// =====================================================================
__global__ void __launch_bounds__(1024, 1)
select_kernel(const float* __restrict__ conf_th_p) {
    const int pair = blockIdx.x;
    const int b = pair >> 2;
    const int tid = threadIdx.x;
    const float conf_th = *conf_th_p;

    extern __shared__ char sm[];
    int* hist = (int*)sm;       // 16384 ints = 64 KB
    u64* keys = (u64*)sm;       // aliases hist after scan

    __shared__ int scanA[1024];
    __shared__ int s_T, s_cnt;

    const float* sc = g_scores + (size_t)pair * PDIM;

    // histogram
    for (int i = tid; i < NBINS; i += 1024) hist[i] = 0;
    __syncthreads();
    for (int p = tid; p < PDIM; p += 1024) {
        float s = sc[p];
        if (s >= conf_th) {
            int bin = (int)(s * 16384.0f);
            if (bin > NBINS - 1) bin = NBINS - 1;
            atomicAdd(&hist[bin], 1);
        }
    }
    __syncthreads();

    // suffix scan -> cutoff bin T
    int base = tid * 16;
    int ps = 0;
#pragma unroll
    for (int k = 0; k < 16; k++) ps += hist[base + k];
    scanA[tid] = ps;
    __syncthreads();
    for (int off = 1; off < 1024; off <<= 1) {
        int v = scanA[tid];
        if (tid + off < 1024) v += scanA[tid + off];
        __syncthreads();
        scanA[tid] = v;
        __syncthreads();
    }
    int total = scanA[0];
    if (tid == 0) { s_T = 0; s_cnt = 0; }
    __syncthreads();
    if (total >= TOPK) {
        int after = (tid < 1023) ? scanA[tid + 1] : 0;
        if (after < TOPK && after + ps >= TOPK) {
            int acc = after;
            for (int bb = 15; bb >= 0; bb--) {
                acc += hist[base + bb];
                if (acc >= TOPK) { s_T = base + bb; break; }
            }
        }
    }
    __syncthreads();
    int T = s_T;

    // gather candidates: key = score_bits<<32 | ~idx (desc == lax.top_k)
    for (int p = tid; p < PDIM; p += 1024) {
        float s = sc[p];
        if (s >= conf_th) {
            int bin = (int)(s * 16384.0f);
            if (bin > NBINS - 1) bin = NBINS - 1;
            if (bin >= T) {
                int pos = atomicAdd(&s_cnt, 1);
                if (pos < CAP)
                    keys[pos] = ((u64)__float_as_uint(s) << 32) | (u32)(~(u32)p);
            }
        }
    }
    __syncthreads();
    int M = s_cnt; if (M > CAP) M = CAP;
    int S = 1024;
    while (S < M) S <<= 1;          // 1024/2048/4096
    for (int i = M + tid; i < S; i += 1024) keys[i] = 0ull;
    __syncthreads();

    // bitonic sort, descending, S elements
    for (int k2 = 2; k2 <= S; k2 <<= 1) {
        for (int j = k2 >> 1; j > 0; j >>= 1) {
            for (int i = tid; i < S; i += 1024) {
                int ixj = i ^ j;
                if (ixj > i) {
                    u64 a = keys[i], c = keys[ixj];
                    bool up = ((i & k2) == 0);
                    bool sw = up ? (a < c) : (a > c);
                    if (sw) { keys[i] = c; keys[ixj] = a; }
                }
            }
            __syncthreads();
        }
    }

    int Kv = (M < TOPK) ? M : TOPK;

    // emit candidates (zero-padded to 1024)
    int i = tid;
    if (i < 1024) {
        size_t o = (size_t)pair * 1024 + i;
        if (i < Kv) {
            u64 key = keys[i];
            int p = (int)(~(u32)key);
            float s = __uint_as_float((u32)(key >> 32));
            float4 csv = g_cs[(size_t)b * PDIM + p];
            float hw = __fmul_rn(csv.z, 0.5f);
            float hh = __fmul_rn(csv.w, 0.5f);
            float X1 = __fsub_rn(csv.x, hw);
            float Y1 = __fsub_rn(csv.y, hh);
            float X2 = __fadd_rn(csv.x, hw);
            float Y2 = __fadd_rn(csv.y, hh);
            g_box[o] = make_float4(X1, Y1, X2, Y2);
            g_area[o] = __fmul_rn(fmaxf(__fsub_rn(X2, X1), 0.0f),
                                  fmaxf(__fsub_rn(Y2, Y1), 0.0f));
            g_cscand[o] = csv;
            g_score[o] = s;
        } else {
            g_box[o] = make_float4(0.f, 0.f, 0.f, 0.f);
            g_area[o] = 0.f;
            g_cscand[o] = make_float4(0.f, 0.f, 0.f, 0.f);
            g_score[o] = 0.f;
        }
    }
    if (tid == 0) g_kv[pair] = Kv;
}

// =====================================================================
// Kernel 3: suppression bitmask, full chip. 512 CTAs = 32 pairs x 16
// chunks, interleaved (i,w) task striding. Division-free decision with
// exact __fdiv_rn fallback in a +-2e-6 guard band (bit-exact vs ref).
// =====================================================================
__global__ void __launch_bounds__(512)
mask_kernel(const float* __restrict__ nms_th_p) {
    const int pair = blockIdx.x & (NPAIR - 1);
    const int chunk = blockIdx.x >> 5;
    const float th = *nms_th_p;

    __shared__ float4 sbox[1024];
    __shared__ float  sarea[1024];

    const int Kv = g_kv[pair];
    for (int i = threadIdx.x; i < 1024; i += 512) {
        sbox[i]  = g_box[(size_t)pair * 1024 + i];
        sarea[i] = g_area[(size_t)pair * 1024 + i];
    }
    __syncthreads();

    u64* mrow = g_mask + (size_t)pair * TOPK * NWORDS;
    const int NT = Kv * NWORDS;
    for (int t = chunk * 512 + threadIdx.x; t < NT; t += MCHUNK * 512) {
        int i = t >> 4;
        int w = t & (NWORDS - 1);
        u64 mword = 0ull;
        int j0 = w << 6;
        int jend = j0 + 64; if (jend > Kv) jend = Kv;
        int jstart = (j0 > i + 1) ? j0 : (i + 1);
        if (jstart < jend) {
            float4 bi = sbox[i];
            float ai = sarea[i];
            for (int j = jstart; j < jend; j++) {
                float4 bj = sbox[j];
                float iw = fmaxf(__fsub_rn(fminf(bi.z, bj.z), fmaxf(bi.x, bj.x)), 0.0f);
                float ih = fmaxf(__fsub_rn(fminf(bi.w, bj.w), fmaxf(bi.y, bj.y)), 0.0f);
                float inter = __fmul_rn(iw, ih);
                float uni = fmaxf(__fsub_rn(__fadd_rn(ai, sarea[j]), inter), 1e-12f);
                float bb = __fmul_rn(th, uni);
                bool sup;
                if (inter > __fmul_rn(bb, 1.000002f)) sup = true;
                else if (inter < __fmul_rn(bb, 0.999998f)) sup = false;
                else sup = (__fdiv_rn(inter, uni) > th);   // rare exact path
                if (sup) mword |= (1ull << (j - j0));
            }
        }
        mrow[t] = mword;
    }
}

// =====================================================================
// Kernel 4: greedy sweep (warp 0, 8-row register prefetch ring, u32
// keep words) + compaction. 32 CTAs.
// =====================================================================
__global__ void __launch_bounds__(1024)
sweep_kernel(float* __restrict__ out) {
    const int pair = blockIdx.x;
    const int tid = threadIdx.x;
    __shared__ u32 s_keep[32];
    __shared__ int s_pref[32];

    const int Kv = g_kv[pair];
    float* outp = out + (size_t)pair * TOPK * 5;
    for (int i = tid; i < TOPK * 5; i += 1024) outp[i] = 0.0f;

    if (tid < 32) {
        const int lane = tid;
        const u32* mb = (const u32*)(g_mask + (size_t)pair * TOPK * NWORDS);
        int n = Kv - (lane << 5);
        u32 keepw = (n >= 32) ? 0xffffffffu : (n > 0 ? ((1u << n) - 1u) : 0u);
        u32 r[8];
#pragma unroll
        for (int k = 0; k < 8; k++) r[k] = (k < Kv) ? mb[k * 32 + lane] : 0u;
#pragma unroll 8
        for (int i = 0; i < Kv; i++) {
            u32 m = r[i & 7];
            int nx = i + 8;
            r[i & 7] = (nx < Kv) ? mb[nx * 32 + lane] : 0u;
            u32 kw = __shfl_sync(0xffffffffu, keepw, (i >> 5) & 31);
            if ((kw >> (i & 31)) & 1u) keepw &= ~m;
        }
        s_keep[lane] = keepw;
    }
    __syncthreads();
    if (tid == 0) {
        int acc = 0;
        for (int w = 0; w < 32; w++) { s_pref[w] = acc; acc += __popc(s_keep[w]); }
    }
    __syncthreads();

    for (int i = tid; i < Kv; i += 1024) {
        u32 kw = s_keep[i >> 5];
        if ((kw >> (i & 31)) & 1u) {
            int pos = s_pref[i >> 5] + __popc(kw & ((1u << (i & 31)) - 1u));
            float4 cs = g_cscand[(size_t)pair * 1024 + i];
            float* rr = outp + pos * 5;
            rr[0] = g_score[(size_t)pair * 1024 + i];
            rr[1] = cs.x; rr[2] = cs.y; rr[3] = cs.z; rr[4] = cs.w;
        }
    }
}

extern "C" void kernel_launch(void* const* d_in, const int* in_sizes, int n_in,
                              void* d_out, int out_size) {
    const float* loc   = (const float*)d_in[0];
    const float* conf  = (const float*)d_in[1];
    const float* prior = (const float*)d_in[2];
    const float* cth   = (const float*)d_in[3];
    const float* nth   = (const float*)d_in[4];
    float* out = (float*)d_out;

    cudaFuncSetAttribute(select_kernel,
                         cudaFuncAttributeMaxDynamicSharedMemorySize, 65536);

    int total = BDIM * PDIM;
    decode_score_kernel<<<(total + 255) / 256, 256>>>(loc, conf, prior);
    select_kernel<<<NPAIR, 1024, 65536>>>(cth);
    mask_kernel<<<NPAIR * MCHUNK, 512>>>(nth);
    sweep_kernel<<<NPAIR, 1024>>>(out);
}